// round 6
// baseline (speedup 1.0000x reference)
#include <cuda_runtime.h>
#include <cuda_bf16.h>
#include <cstdint>
#include <math.h>

#define D        10
#define NUMF     16
#define DIN      36
#define H        128
#define CS1      1
#define CS2      3
#define TILE_M   128
#define THREADS  256

#define E1_TOK (TILE_M + 2*CS1)   // 130
#define E2_TOK (TILE_M + 2*CS2)   // 134
#define EPAD   11
#define SA     84                  // A row stride bytes (21 words: odd -> conflict-free writes)

// ---- dynamic smem layout ----
#define A_BYTES  (TILE_M * SA)                     // 10752
#define OFF_AH0  0
#define OFF_AL0  (A_BYTES)
#define OFF_AH1  (2*A_BYTES)
#define OFF_AL1  (3*A_BYTES)
#define OFF_E1   (4*A_BYTES)                       // 43008
#define OFF_E2   (OFF_E1 + E1_TOK*EPAD*4)          // 48728
#define OFF_T1   (OFF_E2 + E2_TOK*EPAD*4)          // 54624
#define OFF_T2   (OFF_T1 + E1_TOK*4)               // 55144
#define OFF_PART ((OFF_T2 + E2_TOK*4 + 15) & ~15)  // 55680
#define SMEM_TOTAL (OFF_PART + 4*TILE_M*4)         // 57728

// ---- named barriers ----
// FULL(buf)=1+buf : producer arrives(256), consumer syncs(256)
// EMPTY(buf)=3+buf: consumer arrives(256), producer syncs(256)
// 5: producer-internal sync(128) ; 6: consumer-internal sync(128)
__device__ __forceinline__ void bar_sync(int id, int cnt) {
    asm volatile("bar.sync %0, %1;" :: "r"(id), "r"(cnt) : "memory");
}
__device__ __forceinline__ void bar_arrive(int id, int cnt) {
    asm volatile("bar.arrive %0, %1;" :: "r"(id), "r"(cnt) : "memory");
}

__device__ __forceinline__ uint32_t bf16pair(float a, float b) {
    __nv_bfloat16 ha = __float2bfloat16_rn(a), hb = __float2bfloat16_rn(b);
    return (uint32_t)__bfloat16_as_ushort(ha) | ((uint32_t)__bfloat16_as_ushort(hb) << 16);
}
__device__ __forceinline__ void split_pair(float a, float b, uint32_t& hi, uint32_t& lo) {
    __nv_bfloat16 ha = __float2bfloat16_rn(a), hb = __float2bfloat16_rn(b);
    hi = (uint32_t)__bfloat16_as_ushort(ha) | ((uint32_t)__bfloat16_as_ushort(hb) << 16);
    lo = bf16pair(a - __bfloat162float(ha), b - __bfloat162float(hb));
}

__device__ __forceinline__ void mma16(float d[4],
                                      uint32_t a0, uint32_t a1, uint32_t a2, uint32_t a3,
                                      uint32_t b0, uint32_t b1) {
    asm volatile(
        "mma.sync.aligned.m16n8k16.row.col.f32.bf16.bf16.f32 "
        "{%0,%1,%2,%3}, {%4,%5,%6,%7}, {%8,%9}, {%0,%1,%2,%3};"
        : "+f"(d[0]), "+f"(d[1]), "+f"(d[2]), "+f"(d[3])
        : "r"(a0), "r"(a1), "r"(a2), "r"(a3), "r"(b0), "r"(b1));
}
__device__ __forceinline__ void mma8(float d[4], uint32_t a0, uint32_t a1, uint32_t b0) {
    asm volatile(
        "mma.sync.aligned.m16n8k8.row.col.f32.bf16.bf16.f32 "
        "{%0,%1,%2,%3}, {%4,%5}, {%6}, {%0,%1,%2,%3};"
        : "+f"(d[0]), "+f"(d[1]), "+f"(d[2]), "+f"(d[3])
        : "r"(a0), "r"(a1), "r"(b0));
}

__global__ __launch_bounds__(THREADS, 3)
void wordemb_ws_kernel(
    const int*   __restrict__ t1,
    const int*   __restrict__ t2,
    const float* __restrict__ numf,
    const float* __restrict__ T1,
    const float* __restrict__ T2,
    const float* __restrict__ W1,   // [36][128]
    const float* __restrict__ b1,   // [128]
    const float* __restrict__ W2,   // [128]
    const float* __restrict__ b2,   // [1]
    float* __restrict__ out,
    int n, int nTiles)
{
    extern __shared__ char sm[];
    const int tid = threadIdx.x;

    if (tid < 128) {
        // ======================= CONSUMER (warps 0-3) =======================
        const int wid  = tid >> 5;
        const int lane = tid & 31;

        // unblock producer for both buffers immediately
        bar_arrive(3, 256);
        bar_arrive(4, 256);

        // build B fragments once (k0 = p*8 + ksub, bias folded at k==36)
        uint32_t Bhi[4][5], Blo[4][5];
        float w2r[4][2];
        {
            const int nsub = lane >> 2;
            const int ksub = (lane & 3) * 2;
            #pragma unroll
            for (int j = 0; j < 4; j++) {
                int nn = wid * 32 + j * 8 + nsub;
                #pragma unroll
                for (int p = 0; p < 5; p++) {
                    int k0 = p * 8 + ksub;
                    float wv0 = (k0     < DIN) ? W1[k0 * H + nn]     : ((k0     == DIN) ? b1[nn] : 0.0f);
                    float wv1 = (k0 + 1 < DIN) ? W1[(k0 + 1)*H + nn] : ((k0 + 1 == DIN) ? b1[nn] : 0.0f);
                    split_pair(wv0, wv1, Bhi[j][p], Blo[j][p]);
                }
                int nc = wid * 32 + j * 8 + (lane & 3) * 2;
                w2r[j][0] = W2[nc];
                w2r[j][1] = W2[nc + 1];
            }
        }
        const float b2v = b2[0];
        float* s_part = reinterpret_cast<float*>(sm + OFF_PART);

        const int arow = lane >> 2;
        const int acol = (lane & 3) * 4;

        int buf = 0;
        for (int tile = blockIdx.x; tile < nTiles; tile += gridDim.x) {
            bar_sync(1 + buf, 256);   // wait FULL(buf)

            const char* Ah = sm + (buf ? OFF_AH1 : OFF_AH0);
            const char* Al = sm + (buf ? OFF_AL1 : OFF_AL0);

            #pragma unroll
            for (int mt = 0; mt < 8; mt++) {
                float Dacc[4][4];
                #pragma unroll
                for (int j = 0; j < 4; j++) {
                    Dacc[j][0] = 0.f; Dacc[j][1] = 0.f; Dacc[j][2] = 0.f; Dacc[j][3] = 0.f;
                }
                const int rb = mt * 16 + arow;
                const char* r0h = Ah + rb * SA;
                const char* r8h = Ah + (rb + 8) * SA;
                const char* r0l = Al + rb * SA;
                const char* r8l = Al + (rb + 8) * SA;

                #pragma unroll
                for (int s = 0; s < 2; s++) {
                    const int cb = s * 32 + acol;
                    uint32_t ah0 = *(const uint32_t*)(r0h + cb);
                    uint32_t ah1 = *(const uint32_t*)(r8h + cb);
                    uint32_t ah2 = *(const uint32_t*)(r0h + cb + 16);
                    uint32_t ah3 = *(const uint32_t*)(r8h + cb + 16);
                    uint32_t al0 = *(const uint32_t*)(r0l + cb);
                    uint32_t al1 = *(const uint32_t*)(r8l + cb);
                    uint32_t al2 = *(const uint32_t*)(r0l + cb + 16);
                    uint32_t al3 = *(const uint32_t*)(r8l + cb + 16);
                    #pragma unroll
                    for (int j = 0; j < 4; j++)
                        mma16(Dacc[j], ah0, ah1, ah2, ah3, Bhi[j][2*s], Bhi[j][2*s + 1]);
                    #pragma unroll
                    for (int j = 0; j < 4; j++)
                        mma16(Dacc[j], ah0, ah1, ah2, ah3, Blo[j][2*s], Blo[j][2*s + 1]);
                    #pragma unroll
                    for (int j = 0; j < 4; j++)
                        mma16(Dacc[j], al0, al1, al2, al3, Bhi[j][2*s], Bhi[j][2*s + 1]);
                }
                {   // k8 step: k = 32..39 (bias at 36)
                    const int cb = 64 + acol;
                    uint32_t ah0 = *(const uint32_t*)(r0h + cb);
                    uint32_t ah1 = *(const uint32_t*)(r8h + cb);
                    uint32_t al0 = *(const uint32_t*)(r0l + cb);
                    uint32_t al1 = *(const uint32_t*)(r8l + cb);
                    #pragma unroll
                    for (int j = 0; j < 4; j++) mma8(Dacc[j], ah0, ah1, Bhi[j][4]);
                    #pragma unroll
                    for (int j = 0; j < 4; j++) mma8(Dacc[j], ah0, ah1, Blo[j][4]);
                    #pragma unroll
                    for (int j = 0; j < 4; j++) mma8(Dacc[j], al0, al1, Bhi[j][4]);
                }

                float p0 = 0.0f, p1 = 0.0f;
                #pragma unroll
                for (int j = 0; j < 4; j++) {
                    p0 = fmaf(fmaxf(Dacc[j][0], 0.f), w2r[j][0], p0);
                    p0 = fmaf(fmaxf(Dacc[j][1], 0.f), w2r[j][1], p0);
                    p1 = fmaf(fmaxf(Dacc[j][2], 0.f), w2r[j][0], p1);
                    p1 = fmaf(fmaxf(Dacc[j][3], 0.f), w2r[j][1], p1);
                }
                p0 += __shfl_xor_sync(0xFFFFFFFF, p0, 1);
                p0 += __shfl_xor_sync(0xFFFFFFFF, p0, 2);
                p1 += __shfl_xor_sync(0xFFFFFFFF, p1, 1);
                p1 += __shfl_xor_sync(0xFFFFFFFF, p1, 2);
                if ((lane & 3) == 0) {
                    s_part[wid * TILE_M + rb]     = p0;
                    s_part[wid * TILE_M + rb + 8] = p1;
                }
            }

            bar_sync(6, 128);   // consumer-internal: s_part visible

            int i = tile * TILE_M + tid;
            if (i < n) {
                float s = s_part[0*TILE_M + tid] + s_part[1*TILE_M + tid]
                        + s_part[2*TILE_M + tid] + s_part[3*TILE_M + tid] + b2v;
                out[i] = __fdividef(1.0f, 1.0f + __expf(-s));
            }

            bar_arrive(3 + buf, 256);   // EMPTY(buf)
            buf ^= 1;
        }
    } else {
        // ======================= PRODUCER (warps 4-7) =======================
        const int ptid = tid - 128;
        float* s_e1 = reinterpret_cast<float*>(sm + OFF_E1);
        float* s_e2 = reinterpret_cast<float*>(sm + OFF_E2);
        int*   s_tk1 = reinterpret_cast<int*>(sm + OFF_T1);
        int*   s_tk2 = reinterpret_cast<int*>(sm + OFF_T2);
        const float2* T1f2 = reinterpret_cast<const float2*>(T1);
        const float2* T2f2 = reinterpret_cast<const float2*>(T2);

        int buf = 0;
        for (int tile = blockIdx.x; tile < nTiles; tile += gridDim.x) {
            bar_sync(3 + buf, 256);   // wait EMPTY(buf)

            const int r0g = tile * TILE_M;

            // ---- stage tokens ----
            for (int r = ptid; r < E1_TOK; r += 128) {
                int g = r0g - CS1 + r;
                s_tk1[r] = (g >= 0 && g < n) ? t1[g] : -1;
            }
            for (int r = ptid; r < E2_TOK; r += 128) {
                int g = r0g - CS2 + r;
                s_tk2[r] = (g >= 0 && g < n) ? t2[g] : -1;
            }
            bar_sync(5, 128);

            // ---- gather embeddings ----
            for (int e = ptid; e < E1_TOK * 5; e += 128) {
                int r = e / 5, q = e - r * 5;
                int tok = s_tk1[r];
                float2 v = (tok >= 0) ? T1f2[tok * 5 + q] : make_float2(0.0f, 0.0f);
                s_e1[r * EPAD + 2*q]     = v.x;
                s_e1[r * EPAD + 2*q + 1] = v.y;
            }
            for (int e = ptid; e < E2_TOK * 5; e += 128) {
                int r = e / 5, q = e - r * 5;
                int tok = s_tk2[r];
                float2 v = (tok >= 0) ? T2f2[tok * 5 + q] : make_float2(0.0f, 0.0f);
                s_e2[r * EPAD + 2*q]     = v.x;
                s_e2[r * EPAD + 2*q + 1] = v.y;
            }
            bar_sync(5, 128);

            // ---- x-build row ptid -> A[buf] ----
            {
                char* Ah = sm + (buf ? OFF_AH1 : OFF_AH0);
                char* Al = sm + (buf ? OFF_AL1 : OFF_AL0);
                char* rowh = Ah + ptid * SA;
                char* rowl = Al + ptid * SA;

                const int i = r0g + ptid;
                int lo1 = max(i - CS1, 0), hi1 = min(i + CS1 + 1, n);
                int lo2 = max(i - CS2, 0), hi2 = min(i + CS2 + 1, n);
                float inv1 = __fdividef(1.0f, (float)max(hi1 - lo1, 1));
                float inv2 = __fdividef(1.0f, (float)max(hi2 - lo2, 1));

                #pragma unroll
                for (int q = 0; q < 5; q++) {        // e1 -> pairs 0..4
                    float sa = 0.0f, sb = 0.0f;
                    #pragma unroll
                    for (int w = 0; w < 3; w++) {
                        sa += s_e1[(ptid + w) * EPAD + 2*q];
                        sb += s_e1[(ptid + w) * EPAD + 2*q + 1];
                    }
                    uint32_t hi, lo;
                    split_pair(sa * inv1, sb * inv1, hi, lo);
                    *reinterpret_cast<uint32_t*>(rowh + 4*q) = hi;
                    *reinterpret_cast<uint32_t*>(rowl + 4*q) = lo;
                }
                #pragma unroll
                for (int q = 0; q < 5; q++) {        // e2 -> pairs 5..9
                    float sa = 0.0f, sb = 0.0f;
                    #pragma unroll
                    for (int w = 0; w < 7; w++) {
                        sa += s_e2[(ptid + w) * EPAD + 2*q];
                        sb += s_e2[(ptid + w) * EPAD + 2*q + 1];
                    }
                    uint32_t hi, lo;
                    split_pair(sa * inv2, sb * inv2, hi, lo);
                    *reinterpret_cast<uint32_t*>(rowh + 4*(5 + q)) = hi;
                    *reinterpret_cast<uint32_t*>(rowl + 4*(5 + q)) = lo;
                }
                if (i < n) {                          // numeric -> pairs 10..17
                    const float4* nf = reinterpret_cast<const float4*>(numf) + (size_t)i * (NUMF / 4);
                    #pragma unroll
                    for (int q4 = 0; q4 < 4; q4++) {
                        float4 v = nf[q4];
                        uint32_t hi, lo;
                        split_pair(v.x, v.y, hi, lo);
                        *reinterpret_cast<uint32_t*>(rowh + 4*(10 + 2*q4)) = hi;
                        *reinterpret_cast<uint32_t*>(rowl + 4*(10 + 2*q4)) = lo;
                        split_pair(v.z, v.w, hi, lo);
                        *reinterpret_cast<uint32_t*>(rowh + 4*(11 + 2*q4)) = hi;
                        *reinterpret_cast<uint32_t*>(rowl + 4*(11 + 2*q4)) = lo;
                    }
                } else {
                    #pragma unroll
                    for (int q = 10; q < 18; q++) {
                        *reinterpret_cast<uint32_t*>(rowh + 4*q) = 0u;
                        *reinterpret_cast<uint32_t*>(rowl + 4*q) = 0u;
                    }
                }
                // bias pair (1.0, 0.0) at pair 18 ; zero pair 19
                *reinterpret_cast<uint32_t*>(rowh + 4*18) = 0x00003F80u;
                *reinterpret_cast<uint32_t*>(rowl + 4*18) = 0u;
                *reinterpret_cast<uint32_t*>(rowh + 4*19) = 0u;
                *reinterpret_cast<uint32_t*>(rowl + 4*19) = 0u;
            }

            __threadfence_block();
            bar_arrive(1 + buf, 256);   // FULL(buf)
            buf ^= 1;
        }
    }
}

extern "C" void kernel_launch(void* const* d_in, const int* in_sizes, int n_in,
                              void* d_out, int out_size) {
    const int*   t1   = (const int*)d_in[0];
    const int*   t2   = (const int*)d_in[1];
    const float* numf = (const float*)d_in[2];
    const float* T1   = (const float*)d_in[3];
    const float* T2   = (const float*)d_in[4];
    const float* W1   = (const float*)d_in[5];
    const float* b1   = (const float*)d_in[6];
    const float* W2   = (const float*)d_in[7];
    const float* b2   = (const float*)d_in[8];
    float* out = (float*)d_out;

    int n = in_sizes[0];
    int nTiles = (n + TILE_M - 1) / TILE_M;

    static int attr_set = 0;
    if (!attr_set) {
        cudaFuncSetAttribute(wordemb_ws_kernel,
                             cudaFuncAttributeMaxDynamicSharedMemorySize, SMEM_TOTAL);
        attr_set = 1;
    }

    int grid = 148 * 3;
    if (grid > nTiles) grid = nTiles;
    wordemb_ws_kernel<<<grid, THREADS, SMEM_TOTAL>>>(
        t1, t2, numf, T1, T2, W1, b1, W2, b2, out, n, nTiles);
}